// round 14
// baseline (speedup 1.0000x reference)
#include <cuda_runtime.h>
#include <cuda_fp16.h>

#define NN   100000
#define EE   800000
#define D    64
#define CD   256          // (HOPS+1)*D
#define NG   64
#define EMBD 128
#define PB   512          // prepB persistent blocks
#define CH   196          // nodes per prepB chunk (512*196 >= NN)

// Persistent scratch
__device__ float  d_F[(size_t)NN * CD];   // concat features [N][256] fp32
__device__ __half d_Fh[(size_t)NN * CD];  // fp16 mirror (gather source)
__device__ float  d_Wt[3 * 16384];        // permuted weights [L][kq][c][4k]
__device__ int    d_cnt[NN];
__device__ int    d_cur[NN];
__device__ int    d_off[NN + 1];
__device__ int2   d_csrw[EE];             // per-edge {src, dn[src] bits}
__device__ int    d_bsum[PB];
__device__ float  d_dn[NN];
__device__ float  d_gsum[NG * D];
__device__ int    d_bar_cnt = 0;
__device__ int    d_bar_gen = 0;

// ---------------------------------------------------------------------------
__device__ __forceinline__ void upk2(unsigned long long v, float& lo, float& hi) {
    asm("mov.b64 {%0,%1}, %2;" : "=f"(lo), "=f"(hi) : "l"(v));
}
__device__ __forceinline__ void ffma2(unsigned long long& d, unsigned long long a,
                                      unsigned long long b) {
    asm("fma.rn.f32x2 %0, %1, %2, %0;" : "+l"(d) : "l"(a), "l"(b));
}
__device__ __forceinline__ void cpa16(unsigned int saddr, const void* gaddr) {
    asm volatile("cp.async.cg.shared.global [%0], [%1], 16;" :: "r"(saddr), "l"(gaddr));
}
__device__ __forceinline__ void cpa_commit() {
    asm volatile("cp.async.commit_group;");
}
template <int N> __device__ __forceinline__ void cpa_wait() {
    asm volatile("cp.async.wait_group %0;" :: "n"(N));
}

// Software grid barrier; all nblk blocks co-resident.
__device__ __forceinline__ void gbar(int nblk) {
    __threadfence();
    __syncthreads();
    if (threadIdx.x == 0) {
        int g = *((volatile int*)&d_bar_gen);
        int r = atomicAdd(&d_bar_cnt, 1);
        if (r == nblk - 1) {
            d_bar_cnt = 0;
            __threadfence();
            atomicAdd(&d_bar_gen, 1);
        } else {
            while (*((volatile int*)&d_bar_gen) == g) {}
        }
    }
    __syncthreads();
}

// ---------------------------------------------------------------------------
// prep0: copy h into F slot0 (+fp16 mirror), zero counters/gsum, permute W
__global__ void k_prep0(const float* __restrict__ h, const float* __restrict__ W0,
                        const float* __restrict__ W1, const float* __restrict__ W2) {
    int i = blockIdx.x * blockDim.x + threadIdx.x;
    if (i < NN * 16) {
        int r = i >> 4, p = i & 15;
        float4 v = ((const float4*)h)[i];
        ((float4*)d_F)[(size_t)r * 64 + p] = v;
        __half2 h0 = __floats2half2_rn(v.x, v.y);
        __half2 h1 = __floats2half2_rn(v.z, v.w);
        uint2 u;
        u.x = *(unsigned*)&h0;
        u.y = *(unsigned*)&h1;
        ((uint2*)d_Fh)[(size_t)r * 64 + p] = u;
    }
    if (i < NN) { d_cnt[i] = 0; d_cur[i] = 0; }
    if (i < NG * D) d_gsum[i] = 0.f;
    if (i < 3 * 16384) {
        int L = i / 16384, gi = i - L * 16384;
        int kq = gi >> 8, r = gi & 255;
        int c = r >> 2, kk = r & 3;
        const float* W = (L == 0) ? W0 : (L == 1) ? W1 : W2;
        d_Wt[i] = W[(kq * 4 + kk) * 64 + c];
    }
}

// prepB (persistent): count -> scan(off,dn) -> CSR fill with fused {src, dn[src]}
__global__ void __launch_bounds__(256, 4) k_prepB(const int* __restrict__ src,
                                                  const int* __restrict__ dst) {
    __shared__ int sh[256];
    int tid = threadIdx.x, b = blockIdx.x;
    int gt = b * 256 + tid;
    const int GS = PB * 256;

    for (int e = gt; e < EE; e += GS) atomicAdd(&d_cnt[dst[e]], 1);
    gbar(PB);

    {   // per-block chunk sums
        int i0 = b * CH;
        int v = 0;
        if (tid < CH && i0 + tid < NN) v = d_cnt[i0 + tid];
        sh[tid] = v;
        __syncthreads();
        for (int st = 128; st > 0; st >>= 1) {
            if (tid < st) sh[tid] += sh[tid + st];
            __syncthreads();
        }
        if (tid == 0) d_bsum[b] = sh[0];
    }
    gbar(PB);

    {   // exclusive prefix + deg_norm
        int part = 0;
        for (int i = tid; i < b; i += 256) part += d_bsum[i];
        sh[tid] = part;
        __syncthreads();
        for (int st = 128; st > 0; st >>= 1) {
            if (tid < st) sh[tid] += sh[tid + st];
            __syncthreads();
        }
        int base = sh[0];
        __syncthreads();

        int i0 = b * CH, idx = i0 + tid;
        int v = (tid < CH && idx < NN) ? d_cnt[idx] : 0;
        sh[tid] = v;
        __syncthreads();
        for (int st = 1; st < 256; st <<= 1) {
            int a = (tid >= st) ? sh[tid - st] : 0;
            __syncthreads();
            sh[tid] += a;
            __syncthreads();
        }
        if (tid < CH && idx < NN) {
            d_off[idx] = base + sh[tid] - v;
            d_dn[idx] = rsqrtf(fmaxf((float)v, 1.0f));
        }
        if (gt == 0) d_off[NN] = EE;
    }
    gbar(PB);

    for (int e = gt; e < EE; e += GS) {
        int dd = dst[e];
        int s = src[e];
        int p = atomicAdd(&d_cur[dd], 1);
        d_csrw[d_off[dd] + p] = make_int2(s, __float_as_int(d_dn[s]));
    }
}

// ---------------------------------------------------------------------------
// Hop v5: half-warp per node; fp16 message gathers (128B/row) with a depth-2
// software pipeline (v-loads issued ~2 iterations before use). fp32 accumulate.
__global__ void __launch_bounds__(256) k_hop(int hop) {
    int node = blockIdx.x * 16 + (threadIdx.x >> 4);    // grid 6250*16 == NN
    int lane = threadIdx.x & 15;
    int e0 = __ldg(d_off + node);
    int e1 = __ldg(d_off + node + 1);
    const uint2* M = (const uint2*)d_Fh;                // 64 uint2 per node
    int slot_in = (hop - 1) * 16 + lane;

    float4 accA = make_float4(0.f, 0.f, 0.f, 0.f);
    float4 accB = make_float4(0.f, 0.f, 0.f, 0.f);

    const int2 z = make_int2(0, 0);   // src 0 (valid row), weight 0 -> no-op edge
    int2 p0a = z, p0b = z, p1a = z, p1b = z, p2a = z, p2b = z;
    if (e0     < e1) p0a = __ldg(d_csrw + e0);
    if (e0 + 1 < e1) p0b = __ldg(d_csrw + e0 + 1);
    if (e0 + 2 < e1) p1a = __ldg(d_csrw + e0 + 2);
    if (e0 + 3 < e1) p1b = __ldg(d_csrw + e0 + 3);
    if (e0 + 4 < e1) p2a = __ldg(d_csrw + e0 + 4);
    if (e0 + 5 < e1) p2b = __ldg(d_csrw + e0 + 5);
    uint2 v0a = __ldg(M + (size_t)p0a.x * 64 + slot_in);
    uint2 v0b = __ldg(M + (size_t)p0b.x * 64 + slot_in);
    uint2 v1a = __ldg(M + (size_t)p1a.x * 64 + slot_in);
    uint2 v1b = __ldg(M + (size_t)p1b.x * 64 + slot_in);

    for (int e = e0; e < e1; e += 2) {
        // issue pair-(i+2) gathers and pair-(i+3) index loads before consuming pair i
        uint2 v2a = __ldg(M + (size_t)p2a.x * 64 + slot_in);
        uint2 v2b = __ldg(M + (size_t)p2b.x * 64 + slot_in);
        int2 p3a = z, p3b = z;
        if (e + 6 < e1) p3a = __ldg(d_csrw + e + 6);
        if (e + 7 < e1) p3b = __ldg(d_csrw + e + 7);

        float wa = __int_as_float(p0a.y);
        float wb = __int_as_float(p0b.y);
        float2 fa0 = __half22float2(*(const __half2*)&v0a.x);
        float2 fa1 = __half22float2(*(const __half2*)&v0a.y);
        float2 fb0 = __half22float2(*(const __half2*)&v0b.x);
        float2 fb1 = __half22float2(*(const __half2*)&v0b.y);
        accA.x = fmaf(fa0.x, wa, accA.x); accA.y = fmaf(fa0.y, wa, accA.y);
        accA.z = fmaf(fa1.x, wa, accA.z); accA.w = fmaf(fa1.y, wa, accA.w);
        accB.x = fmaf(fb0.x, wb, accB.x); accB.y = fmaf(fb0.y, wb, accB.y);
        accB.z = fmaf(fb1.x, wb, accB.z); accB.w = fmaf(fb1.y, wb, accB.w);

        p0a = p1a; p0b = p1b; p1a = p2a; p1b = p2b; p2a = p3a; p2b = p3b;
        v0a = v1a; v0b = v1b; v1a = v2a; v1b = v2b;
    }

    float dn = __ldg(d_dn + node);
    float4 acc;
    acc.x = (accA.x + accB.x) * dn;
    acc.y = (accA.y + accB.y) * dn;
    acc.z = (accA.z + accB.z) * dn;
    acc.w = (accA.w + accB.w) * dn;
    ((float4*)d_F)[(size_t)node * 64 + hop * 16 + lane] = acc;
    __half2 h0 = __floats2half2_rn(acc.x, acc.y);
    __half2 h1 = __floats2half2_rn(acc.z, acc.w);
    uint2 u;
    u.x = *(unsigned*)&h0;
    u.y = *(unsigned*)&h1;
    ((uint2*)d_Fh)[(size_t)node * 64 + hop * 16 + lane] = u;
}

// ---------------------------------------------------------------------------
// GEMM v8 (measured-good): 128 threads / 4 warps; warp = 16 nodes x 64 cols
// (lane owns cols {lane, lane+32}); K chunked x8, X/W double-buffered cp.async.
__global__ void __launch_bounds__(128, 4) k_gemm(int layer, const float* __restrict__ b) {
    __shared__ float4 Xs[2][512];        // [buf][node*8 + f]   8KB per buf
    __shared__ float4 Wsm[2][512];       // [buf][kq*64 + i]    8KB per buf
    int tid = threadIdx.x;
    int lane = tid & 31, warp = tid >> 5;
    int n0 = blockIdx.x * 64;
    int nb = warp * 16;
    const float4* Wt4 = (const float4*)(d_Wt + layer * 16384);
    const float4* F4 = (const float4*)d_F;

    unsigned int xs_s[2], ws_s[2];
    xs_s[0] = (unsigned int)__cvta_generic_to_shared(&Xs[0][0]);
    xs_s[1] = (unsigned int)__cvta_generic_to_shared(&Xs[1][0]);
    ws_s[0] = (unsigned int)__cvta_generic_to_shared(&Wsm[0][0]);
    ws_s[1] = (unsigned int)__cvta_generic_to_shared(&Wsm[1][0]);

    unsigned long long acc0[16], acc1[16];
#pragma unroll
    for (int n = 0; n < 16; n++) { acc0[n] = 0ull; acc1[n] = 0ull; }

    auto stage = [&](int ch, int bf) {
#pragma unroll
        for (int t = 0; t < 4; t++) {
            int i = tid + t * 128;
            int n = i >> 3, f = i & 7;
            int node = n0 + n;
            if (node >= NN) node = NN - 1;        // clamp: no OOB cp.async
            cpa16(xs_s[bf] + i * 16, F4 + (size_t)node * 64 + ch * 8 + f);
        }
#pragma unroll
        for (int t = 0; t < 4; t++) {
            int i = tid + t * 128;
            cpa16(ws_s[bf] + i * 16, Wt4 + ch * 512 + i);
        }
        cpa_commit();
    };

    stage(0, 0);
    for (int ch = 0; ch < 8; ch++) {
        int bf = ch & 1;
        if (ch + 1 < 8) {
            stage(ch + 1, bf ^ 1);
            cpa_wait<1>();
        } else {
            cpa_wait<0>();
        }
        __syncthreads();

        const ulonglong2* Ws2 = (const ulonglong2*)&Wsm[bf][0];
        const float* Xf = (const float*)&Xs[bf][0];
#pragma unroll
        for (int kq = 0; kq < 8; kq++) {
            ulonglong2 w0 = Ws2[kq * 64 + lane];          // 512B contig, conflict-free
            ulonglong2 w1 = Ws2[kq * 64 + 32 + lane];
#pragma unroll
            for (int n = 0; n < 16; n++) {
                ulonglong2 x = *(const ulonglong2*)(Xf + (nb + n) * 32 + kq * 4); // bcast
                ffma2(acc0[n], x.x, w0.x);
                ffma2(acc0[n], x.y, w0.y);
                ffma2(acc1[n], x.x, w1.x);
                ffma2(acc1[n], x.y, w1.y);
            }
        }
        __syncthreads();
    }

    float bias0 = __ldg(b + lane);
    float bias1 = __ldg(b + 32 + lane);
#pragma unroll
    for (int n = 0; n < 16; n++) {
        int node = n0 + nb + n;
        if (node < NN) {
            float l0, h0, l1, h1;
            upk2(acc0[n], l0, h0);
            upk2(acc1[n], l1, h1);
            float o0 = fmaxf(l0 + h0 + bias0, 0.f);
            float o1 = fmaxf(l1 + h1 + bias1, 0.f);
            float* row = d_F + (size_t)node * CD;
            row[lane]      = o0;
            row[32 + lane] = o1;
            d_Fh[(size_t)node * CD + lane]      = __float2half(o0);
            d_Fh[(size_t)node * CD + 32 + lane] = __float2half(o1);
        }
    }
}

// ---------------------------------------------------------------------------
// Per-graph sums of F slot0 (graph_ids sorted -> running-accumulator flush)
__global__ void k_gsum(const int* __restrict__ gid) {
    const int CHN = 512;
    int c = threadIdx.x & 63;
    int r0 = threadIdx.x >> 6;
    int nbeg = blockIdx.x * CHN + r0;
    int nend = min(NN, blockIdx.x * CHN + CHN);
    float acc = 0.f;
    int cur = -1;
    for (int n = nbeg; n < nend; n += 4) {
        int g = gid[n];
        if (g != cur) {
            if (cur >= 0) atomicAdd(&d_gsum[cur * D + c], acc);
            cur = g; acc = 0.f;
        }
        acc += d_F[(size_t)n * CD + c];
    }
    if (cur >= 0) atomicAdd(&d_gsum[cur * D + c], acc);
}

// Readout: mean -> @embW + embb -> L2 normalize. One block, 256 threads.
__global__ void k_final(const int* __restrict__ gid,
                        const float* __restrict__ embW,
                        const float* __restrict__ embb,
                        float* __restrict__ out) {
    __shared__ float hg[NG][D];
    __shared__ int bnd[NG + 1];
    __shared__ float nrm[NG];
    int tid = threadIdx.x;

    if (tid <= NG) {
        int lo = 0, hi = NN;
        while (lo < hi) {
            int mid = (lo + hi) >> 1;
            if (gid[mid] < tid) lo = mid + 1; else hi = mid;
        }
        bnd[tid] = lo;
    }
    if (tid < NG) nrm[tid] = 0.f;
    __syncthreads();

    for (int idx = tid; idx < NG * D; idx += 256) {
        int g = idx >> 6;
        float cnt = (float)max(bnd[g + 1] - bnd[g], 1);
        hg[g][idx & 63] = d_gsum[idx] / cnt;
    }
    __syncthreads();

    for (int idx = tid; idx < NG * EMBD; idx += 256) {
        int g = idx >> 7, e = idx & 127;
        float s = embb[e];
#pragma unroll 16
        for (int k = 0; k < D; k++) s += hg[g][k] * embW[k * EMBD + e];
        atomicAdd(&nrm[g], s * s);
    }
    __syncthreads();

    for (int idx = tid; idx < NG * EMBD; idx += 256) {
        int g = idx >> 7, e = idx & 127;
        float s = embb[e];
#pragma unroll 16
        for (int k = 0; k < D; k++) s += hg[g][k] * embW[k * EMBD + e];
        float nv = fmaxf(sqrtf(nrm[g]), 1e-12f);
        out[idx] = s / nv;
    }
}

// ---------------------------------------------------------------------------
extern "C" void kernel_launch(void* const* d_in, const int* in_sizes, int n_in,
                              void* d_out, int out_size) {
    const float* h    = (const float*)d_in[0];
    const int*   src  = (const int*)d_in[1];
    const int*   dst  = (const int*)d_in[2];
    const int*   gid  = (const int*)d_in[3];
    const float* Wl[3] = {(const float*)d_in[4], (const float*)d_in[6], (const float*)d_in[8]};
    const float* bl[3] = {(const float*)d_in[5], (const float*)d_in[7], (const float*)d_in[9]};
    const float* embW = (const float*)d_in[10];
    const float* embb = (const float*)d_in[11];
    float* out = (float*)d_out;
    (void)in_sizes; (void)n_in; (void)out_size;

    k_prep0<<<(NN * 16 + 255) / 256, 256>>>(h, Wl[0], Wl[1], Wl[2]);  // 1
    k_prepB<<<PB, 256>>>(src, dst);                                   // 2

    for (int L = 0; L < 3; L++) {
        k_hop<<<NN / 16, 256>>>(1);                                   // 3 (L=0)
        k_hop<<<NN / 16, 256>>>(2);                                   // 4 (L=0) <- profiled
        k_hop<<<NN / 16, 256>>>(3);
        k_gemm<<<(NN + 63) / 64, 128>>>(L, bl[L]);
    }

    k_gsum<<<(NN + 511) / 512, 256>>>(gid);
    k_final<<<1, 256>>>(gid, embW, embb, out);
}

// round 15
// speedup vs baseline: 1.1830x; 1.1830x over previous
#include <cuda_runtime.h>
#include <cuda_bf16.h>

#define NN   100000
#define EE   800000
#define D    64
#define CD   256          // (HOPS+1)*D
#define NG   64
#define EMBD 128
#define PB   512          // prepB persistent blocks
#define CH   196          // nodes per prepB chunk (512*196 >= NN)

// Persistent scratch
__device__ float d_F[(size_t)NN * CD];           // concat features [N][256] fp32
__device__ __nv_bfloat16 d_Wb[3 * 2 * 64 * 256]; // [L][hi/lo][n][k] bf16 split
__device__ int   d_cnt[NN];
__device__ int   d_cur[NN];
__device__ int   d_off[NN + 1];
__device__ int2  d_csrw[EE];                     // per-edge {src, dn[src] bits}
__device__ int   d_bsum[PB];
__device__ float d_dn[NN];
__device__ float d_gsum[NG * D];
__device__ int   d_bar_cnt = 0;
__device__ int   d_bar_gen = 0;

// ---------------------------------------------------------------------------
__device__ __forceinline__ unsigned smem_u32(const void* p) {
    unsigned a;
    asm("{ .reg .u64 t; cvta.to.shared.u64 t, %1; cvt.u32.u64 %0, t; }"
        : "=r"(a) : "l"(p));
    return a;
}
__device__ __forceinline__ void cpa16(unsigned saddr, const void* gaddr) {
    asm volatile("cp.async.cg.shared.global [%0], [%1], 16;" :: "r"(saddr), "l"(gaddr));
}
__device__ __forceinline__ void cpa_commit() { asm volatile("cp.async.commit_group;"); }
template <int N> __device__ __forceinline__ void cpa_wait() {
    asm volatile("cp.async.wait_group %0;" :: "n"(N));
}
__device__ __forceinline__ void ldsm4(unsigned& r0, unsigned& r1, unsigned& r2,
                                      unsigned& r3, unsigned addr) {
    asm volatile("ldmatrix.sync.aligned.m8n8.x4.shared.b16 {%0,%1,%2,%3}, [%4];"
                 : "=r"(r0), "=r"(r1), "=r"(r2), "=r"(r3) : "r"(addr));
}
__device__ __forceinline__ void mma16816(float& c0, float& c1, float& c2, float& c3,
                                         unsigned a0, unsigned a1, unsigned a2,
                                         unsigned a3, unsigned b0, unsigned b1) {
    asm volatile(
        "mma.sync.aligned.m16n8k16.row.col.f32.bf16.bf16.f32 "
        "{%0,%1,%2,%3}, {%4,%5,%6,%7}, {%8,%9}, {%0,%1,%2,%3};"
        : "+f"(c0), "+f"(c1), "+f"(c2), "+f"(c3)
        : "r"(a0), "r"(a1), "r"(a2), "r"(a3), "r"(b0), "r"(b1));
}

// Software grid barrier; all nblk blocks co-resident.
__device__ __forceinline__ void gbar(int nblk) {
    __threadfence();
    __syncthreads();
    if (threadIdx.x == 0) {
        int g = *((volatile int*)&d_bar_gen);
        int r = atomicAdd(&d_bar_cnt, 1);
        if (r == nblk - 1) {
            d_bar_cnt = 0;
            __threadfence();
            atomicAdd(&d_bar_gen, 1);
        } else {
            while (*((volatile int*)&d_bar_gen) == g) {}
        }
    }
    __syncthreads();
}

// ---------------------------------------------------------------------------
// prep0: copy h into F slot0, zero counters/gsum, build Wb = W^T bf16 hi/lo
__global__ void k_prep0(const float* __restrict__ h, const float* __restrict__ W0,
                        const float* __restrict__ W1, const float* __restrict__ W2) {
    int i = blockIdx.x * blockDim.x + threadIdx.x;
    if (i < NN * 16) {
        int r = i >> 4, p = i & 15;
        ((float4*)d_F)[(size_t)r * 64 + p] = ((const float4*)h)[i];
    }
    if (i < NN) { d_cnt[i] = 0; d_cur[i] = 0; }
    if (i < NG * D) d_gsum[i] = 0.f;
    if (i < 3 * 16384) {
        int L = i / 16384, r = i - L * 16384;
        int n = r >> 8, k = r & 255;
        const float* W = (L == 0) ? W0 : (L == 1) ? W1 : W2;
        float w = W[k * 64 + n];
        __nv_bfloat16 hi = __float2bfloat16(w);
        __nv_bfloat16 lo = __float2bfloat16(w - __bfloat162float(hi));
        d_Wb[(L * 2 + 0) * 16384 + n * 256 + k] = hi;
        d_Wb[(L * 2 + 1) * 16384 + n * 256 + k] = lo;
    }
}

// prepB (persistent): count -> scan(off,dn) -> CSR fill with fused {src, dn[src]}
__global__ void __launch_bounds__(256, 4) k_prepB(const int* __restrict__ src,
                                                  const int* __restrict__ dst) {
    __shared__ int sh[256];
    int tid = threadIdx.x, b = blockIdx.x;
    int gt = b * 256 + tid;
    const int GS = PB * 256;

    for (int e = gt; e < EE; e += GS) atomicAdd(&d_cnt[dst[e]], 1);
    gbar(PB);

    {
        int i0 = b * CH;
        int v = 0;
        if (tid < CH && i0 + tid < NN) v = d_cnt[i0 + tid];
        sh[tid] = v;
        __syncthreads();
        for (int st = 128; st > 0; st >>= 1) {
            if (tid < st) sh[tid] += sh[tid + st];
            __syncthreads();
        }
        if (tid == 0) d_bsum[b] = sh[0];
    }
    gbar(PB);

    {
        int part = 0;
        for (int i = tid; i < b; i += 256) part += d_bsum[i];
        sh[tid] = part;
        __syncthreads();
        for (int st = 128; st > 0; st >>= 1) {
            if (tid < st) sh[tid] += sh[tid + st];
            __syncthreads();
        }
        int base = sh[0];
        __syncthreads();

        int i0 = b * CH, idx = i0 + tid;
        int v = (tid < CH && idx < NN) ? d_cnt[idx] : 0;
        sh[tid] = v;
        __syncthreads();
        for (int st = 1; st < 256; st <<= 1) {
            int a = (tid >= st) ? sh[tid - st] : 0;
            __syncthreads();
            sh[tid] += a;
            __syncthreads();
        }
        if (tid < CH && idx < NN) {
            d_off[idx] = base + sh[tid] - v;
            d_dn[idx] = rsqrtf(fmaxf((float)v, 1.0f));
        }
        if (gt == 0) d_off[NN] = EE;
    }
    gbar(PB);

    for (int e = gt; e < EE; e += GS) {
        int dd = dst[e];
        int s = src[e];
        int p = atomicAdd(&d_cur[dd], 1);
        d_csrw[d_off[dd] + p] = make_int2(s, __float_as_int(d_dn[s]));
    }
}

// ---------------------------------------------------------------------------
// Hop v3 (measured 29.8us): half-warp per node, fused {src,w}, dual chains.
__global__ void __launch_bounds__(256) k_hop(int hop) {
    int node = blockIdx.x * 16 + (threadIdx.x >> 4);    // grid 6250*16 == NN
    int lane = threadIdx.x & 15;
    int e0 = __ldg(d_off + node);
    int e1 = __ldg(d_off + node + 1);
    const float4* F4 = (const float4*)d_F;
    int slot_in = (hop - 1) * 16 + lane;

    float4 accA = make_float4(0.f, 0.f, 0.f, 0.f);
    float4 accB = make_float4(0.f, 0.f, 0.f, 0.f);

    int2 p0 = make_int2(0, 0), p1 = make_int2(0, 0);
    if (e0 < e1)     p0 = __ldg(d_csrw + e0);
    if (e0 + 1 < e1) p1 = __ldg(d_csrw + e0 + 1);

    int e = e0;
    for (; e + 2 <= e1; e += 2) {
        int2 pn0 = make_int2(0, 0), pn1 = make_int2(0, 0);
        if (e + 2 < e1) pn0 = __ldg(d_csrw + e + 2);
        if (e + 3 < e1) pn1 = __ldg(d_csrw + e + 3);
        float w0 = __int_as_float(p0.y);
        float w1 = __int_as_float(p1.y);
        float4 v0 = __ldg(F4 + (size_t)p0.x * 64 + slot_in);
        float4 v1 = __ldg(F4 + (size_t)p1.x * 64 + slot_in);
        accA.x = fmaf(v0.x, w0, accA.x); accA.y = fmaf(v0.y, w0, accA.y);
        accA.z = fmaf(v0.z, w0, accA.z); accA.w = fmaf(v0.w, w0, accA.w);
        accB.x = fmaf(v1.x, w1, accB.x); accB.y = fmaf(v1.y, w1, accB.y);
        accB.z = fmaf(v1.z, w1, accB.z); accB.w = fmaf(v1.w, w1, accB.w);
        p0 = pn0; p1 = pn1;
    }
    if (e < e1) {
        float w = __int_as_float(p0.y);
        float4 v = __ldg(F4 + (size_t)p0.x * 64 + slot_in);
        accA.x = fmaf(v.x, w, accA.x); accA.y = fmaf(v.y, w, accA.y);
        accA.z = fmaf(v.z, w, accA.z); accA.w = fmaf(v.w, w, accA.w);
    }

    float dn = __ldg(d_dn + node);
    float4 acc;
    acc.x = (accA.x + accB.x) * dn;
    acc.y = (accA.y + accB.y) * dn;
    acc.z = (accA.z + accB.z) * dn;
    acc.w = (accA.w + accB.w) * dn;
    ((float4*)d_F)[(size_t)node * 64 + hop * 16 + lane] = acc;
}

// ---------------------------------------------------------------------------
// GEMM v9: mma.sync bf16 3-product split. Block = 64 nodes x 64 cols; 4 warps,
// warp = 16 nodes. K chunked x8 (32 k). A: LDG fp32 -> split -> STS bf16;
// B: cp.async of pre-split Wb. 80B-padded smem rows -> conflict-free ldmatrix.
__global__ void __launch_bounds__(128) k_gemmmm(int layer, const float* __restrict__ b) {
    // smem: Ah | Al | Bh | Bl, each 64 rows x 40 bf16 (80B) = 5120B; total 20KB.
    __shared__ __align__(16) __nv_bfloat16 SM[4 * 64 * 40];
    __nv_bfloat16* Ah = SM;
    __nv_bfloat16* Al = SM + 64 * 40;
    __nv_bfloat16* Bh = SM + 2 * 64 * 40;
    __nv_bfloat16* Bl = SM + 3 * 64 * 40;

    int tid = threadIdx.x;
    int lane = tid & 31, warp = tid >> 5;
    int n0 = blockIdx.x * 64;
    const float4* F4 = (const float4*)d_F;
    const __nv_bfloat16* Wh = d_Wb + (layer * 2 + 0) * 16384;
    const __nv_bfloat16* Wl = d_Wb + (layer * 2 + 1) * 16384;

    unsigned ah_s = smem_u32(Ah), al_s = smem_u32(Al);
    unsigned bh_s = smem_u32(Bh), bl_s = smem_u32(Bl);

    float c[8][4];
#pragma unroll
    for (int t = 0; t < 8; t++)
#pragma unroll
        for (int j = 0; j < 4; j++) c[t][j] = 0.f;

    // ldmatrix lane addresses (element offsets computed per kstep below)
    int lr = lane & 15;                  // A: row within warp tile (lanes 0-15)
    int ahalf = (lane >> 4) ? 8 : 0;     // A: +8 k for lanes 16-31
    int bg = lane >> 3, blr = lane & 7;  // B groups
    int bn = ((bg >> 1) ? 8 : 0) + blr;  // B: n within 16-tile pair
    int bk = (bg & 1) ? 8 : 0;           // B: +8 k

    for (int ch = 0; ch < 8; ch++) {
        __syncthreads();                 // previous chunk's compute done
        // stage A: 64 nodes x 32 k fp32 -> bf16 hi/lo
#pragma unroll
        for (int t = 0; t < 4; t++) {
            int i = tid + t * 128;       // 512 float4
            int nd = i >> 3, f = i & 7;
            int node = n0 + nd;
            if (node >= NN) node = NN - 1;
            float4 v = __ldg(F4 + (size_t)node * 64 + ch * 8 + f);
            __nv_bfloat16 h0 = __float2bfloat16(v.x);
            __nv_bfloat16 h1 = __float2bfloat16(v.y);
            __nv_bfloat16 h2 = __float2bfloat16(v.z);
            __nv_bfloat16 h3 = __float2bfloat16(v.w);
            __nv_bfloat16 hv[4] = {h0, h1, h2, h3};
            __nv_bfloat16 lv[4] = {
                __float2bfloat16(v.x - __bfloat162float(h0)),
                __float2bfloat16(v.y - __bfloat162float(h1)),
                __float2bfloat16(v.z - __bfloat162float(h2)),
                __float2bfloat16(v.w - __bfloat162float(h3))};
            *(uint2*)(Ah + nd * 40 + f * 4) = *(uint2*)hv;
            *(uint2*)(Al + nd * 40 + f * 4) = *(uint2*)lv;
        }
        // stage B via cp.async: 512 x 16B (hi 256 + lo 256)
#pragma unroll
        for (int t = 0; t < 4; t++) {
            int i = tid + t * 128;
            int part = i >> 8, r = i & 255;
            int n = r >> 2, j = r & 3;
            const __nv_bfloat16* srcp = (part ? Wl : Wh) + n * 256 + ch * 32 + j * 8;
            unsigned dstp = (part ? bl_s : bh_s) + (unsigned)(n * 80 + j * 16);
            cpa16(dstp, srcp);
        }
        cpa_commit();
        cpa_wait<0>();
        __syncthreads();

        // compute: 2 ksteps of k16
#pragma unroll
        for (int kk = 0; kk < 2; kk++) {
            unsigned a_off = (unsigned)(((warp * 16 + lr) * 40 + kk * 16 + ahalf) * 2);
            unsigned ah0, ah1, ah2, ah3, alo0, alo1, alo2, alo3;
            ldsm4(ah0, ah1, ah2, ah3, ah_s + a_off);
            ldsm4(alo0, alo1, alo2, alo3, al_s + a_off);
#pragma unroll
            for (int nt = 0; nt < 4; nt++) {
                unsigned b_off = (unsigned)(((nt * 16 + bn) * 40 + kk * 16 + bk) * 2);
                unsigned bh0, bh1, bh2, bh3, bl0, bl1, bl2, bl3;
                ldsm4(bh0, bh1, bh2, bh3, bh_s + b_off);
                ldsm4(bl0, bl1, bl2, bl3, bl_s + b_off);
                int t0 = 2 * nt, t1 = 2 * nt + 1;
                mma16816(c[t0][0], c[t0][1], c[t0][2], c[t0][3],
                         ah0, ah1, ah2, ah3, bh0, bh1);
                mma16816(c[t1][0], c[t1][1], c[t1][2], c[t1][3],
                         ah0, ah1, ah2, ah3, bh2, bh3);
                mma16816(c[t0][0], c[t0][1], c[t0][2], c[t0][3],
                         alo0, alo1, alo2, alo3, bh0, bh1);
                mma16816(c[t1][0], c[t1][1], c[t1][2], c[t1][3],
                         alo0, alo1, alo2, alo3, bh2, bh3);
                mma16816(c[t0][0], c[t0][1], c[t0][2], c[t0][3],
                         ah0, ah1, ah2, ah3, bl0, bl1);
                mma16816(c[t1][0], c[t1][1], c[t1][2], c[t1][3],
                         ah0, ah1, ah2, ah3, bl2, bl3);
            }
        }
    }

    // epilogue: C frags -> smem [64][65] -> bias+relu -> F slot0
    __syncthreads();
    float* Ds = (float*)SM;              // 64*65*4 = 16640B <= 20KB
    int q = lane & 3, r = lane >> 2;
#pragma unroll
    for (int nt = 0; nt < 8; nt++) {
        int col = nt * 8 + 2 * q;
        int row = warp * 16 + r;
        Ds[row * 65 + col]           = c[nt][0];
        Ds[row * 65 + col + 1]       = c[nt][1];
        Ds[(row + 8) * 65 + col]     = c[nt][2];
        Ds[(row + 8) * 65 + col + 1] = c[nt][3];
    }
    __syncthreads();
    for (int idx = tid; idx < 64 * 64; idx += 128) {
        int row = idx >> 6, cc = idx & 63;
        int node = n0 + row;
        if (node < NN) {
            float v = Ds[row * 65 + cc] + __ldg(b + cc);
            d_F[(size_t)node * CD + cc] = fmaxf(v, 0.f);
        }
    }
}

// ---------------------------------------------------------------------------
// Per-graph sums of F slot0 (graph_ids sorted -> running-accumulator flush)
__global__ void k_gsum(const int* __restrict__ gid) {
    const int CHN = 512;
    int c = threadIdx.x & 63;
    int r0 = threadIdx.x >> 6;
    int nbeg = blockIdx.x * CHN + r0;
    int nend = min(NN, blockIdx.x * CHN + CHN);
    float acc = 0.f;
    int cur = -1;
    for (int n = nbeg; n < nend; n += 4) {
        int g = gid[n];
        if (g != cur) {
            if (cur >= 0) atomicAdd(&d_gsum[cur * D + c], acc);
            cur = g; acc = 0.f;
        }
        acc += d_F[(size_t)n * CD + c];
    }
    if (cur >= 0) atomicAdd(&d_gsum[cur * D + c], acc);
}

// Readout: mean -> @embW + embb -> L2 normalize. One block, 256 threads.
__global__ void k_final(const int* __restrict__ gid,
                        const float* __restrict__ embW,
                        const float* __restrict__ embb,
                        float* __restrict__ out) {
    __shared__ float hg[NG][D];
    __shared__ int bnd[NG + 1];
    __shared__ float nrm[NG];
    int tid = threadIdx.x;

    if (tid <= NG) {
        int lo = 0, hi = NN;
        while (lo < hi) {
            int mid = (lo + hi) >> 1;
            if (gid[mid] < tid) lo = mid + 1; else hi = mid;
        }
        bnd[tid] = lo;
    }
    if (tid < NG) nrm[tid] = 0.f;
    __syncthreads();

    for (int idx = tid; idx < NG * D; idx += 256) {
        int g = idx >> 6;
        float cnt = (float)max(bnd[g + 1] - bnd[g], 1);
        hg[g][idx & 63] = d_gsum[idx] / cnt;
    }
    __syncthreads();

    for (int idx = tid; idx < NG * EMBD; idx += 256) {
        int g = idx >> 7, e = idx & 127;
        float s = embb[e];
#pragma unroll 16
        for (int k = 0; k < D; k++) s += hg[g][k] * embW[k * EMBD + e];
        atomicAdd(&nrm[g], s * s);
    }
    __syncthreads();

    for (int idx = tid; idx < NG * EMBD; idx += 256) {
        int g = idx >> 7, e = idx & 127;
        float s = embb[e];
#pragma unroll 16
        for (int k = 0; k < D; k++) s += hg[g][k] * embW[k * EMBD + e];
        float nv = fmaxf(sqrtf(nrm[g]), 1e-12f);
        out[idx] = s / nv;
    }
}

// ---------------------------------------------------------------------------
extern "C" void kernel_launch(void* const* d_in, const int* in_sizes, int n_in,
                              void* d_out, int out_size) {
    const float* h    = (const float*)d_in[0];
    const int*   src  = (const int*)d_in[1];
    const int*   dst  = (const int*)d_in[2];
    const int*   gid  = (const int*)d_in[3];
    const float* Wl[3] = {(const float*)d_in[4], (const float*)d_in[6], (const float*)d_in[8]};
    const float* bl[3] = {(const float*)d_in[5], (const float*)d_in[7], (const float*)d_in[9]};
    const float* embW = (const float*)d_in[10];
    const float* embb = (const float*)d_in[11];
    float* out = (float*)d_out;
    (void)in_sizes; (void)n_in; (void)out_size;

    k_prep0<<<(NN * 16 + 255) / 256, 256>>>(h, Wl[0], Wl[1], Wl[2]);  // 1
    k_prepB<<<PB, 256>>>(src, dst);                                   // 2

    for (int L = 0; L < 3; L++) {
        k_hop<<<NN / 16, 256>>>(1);
        k_hop<<<NN / 16, 256>>>(2);
        k_hop<<<NN / 16, 256>>>(3);
        k_gemmmm<<<(NN + 63) / 64, 128>>>(L, bl[L]);
    }

    k_gsum<<<(NN + 511) / 512, 256>>>(gid);
    k_final<<<1, 256>>>(gid, embW, embb, out);
}

// round 16
// speedup vs baseline: 1.2389x; 1.0472x over previous
#include <cuda_runtime.h>
#include <cuda_bf16.h>

#define NN   100000
#define EE   800000
#define D    64
#define CD   256          // (HOPS+1)*D
#define NG   64
#define EMBD 128
#define PB   512          // prepB persistent blocks
#define CH   196          // nodes per prepB chunk (512*196 >= NN)

// Persistent scratch
__device__ float d_F[(size_t)NN * CD];           // concat features [N][256] fp32
__device__ __nv_bfloat16 d_Wb[3 * 2 * 64 * 256]; // [L][hi/lo][n][k] bf16 split
__device__ int   d_cnt[NN];
__device__ int   d_cur[NN];
__device__ int   d_off[NN + 1];
__device__ int2  d_csrw[EE];                     // per-edge {src, dn[src] bits}
__device__ int   d_bsum[PB];
__device__ float d_dn[NN];
__device__ float d_gsum[NG * D];
__device__ int   d_bar_cnt = 0;
__device__ int   d_bar_gen = 0;

// ---------------------------------------------------------------------------
__device__ __forceinline__ unsigned smem_u32(const void* p) {
    unsigned a;
    asm("{ .reg .u64 t; cvta.to.shared.u64 t, %1; cvt.u32.u64 %0, t; }"
        : "=r"(a) : "l"(p));
    return a;
}
__device__ __forceinline__ void cpa16(unsigned saddr, const void* gaddr) {
    asm volatile("cp.async.cg.shared.global [%0], [%1], 16;" :: "r"(saddr), "l"(gaddr));
}
__device__ __forceinline__ void cpa_commit() { asm volatile("cp.async.commit_group;"); }
template <int N> __device__ __forceinline__ void cpa_wait() {
    asm volatile("cp.async.wait_group %0;" :: "n"(N));
}
__device__ __forceinline__ void ldsm4(unsigned& r0, unsigned& r1, unsigned& r2,
                                      unsigned& r3, unsigned addr) {
    asm volatile("ldmatrix.sync.aligned.m8n8.x4.shared.b16 {%0,%1,%2,%3}, [%4];"
                 : "=r"(r0), "=r"(r1), "=r"(r2), "=r"(r3) : "r"(addr));
}
__device__ __forceinline__ void mma16816(float& c0, float& c1, float& c2, float& c3,
                                         unsigned a0, unsigned a1, unsigned a2,
                                         unsigned a3, unsigned b0, unsigned b1) {
    asm volatile(
        "mma.sync.aligned.m16n8k16.row.col.f32.bf16.bf16.f32 "
        "{%0,%1,%2,%3}, {%4,%5,%6,%7}, {%8,%9}, {%0,%1,%2,%3};"
        : "+f"(c0), "+f"(c1), "+f"(c2), "+f"(c3)
        : "r"(a0), "r"(a1), "r"(a2), "r"(a3), "r"(b0), "r"(b1));
}

// Software grid barrier; all nblk blocks co-resident.
__device__ __forceinline__ void gbar(int nblk) {
    __threadfence();
    __syncthreads();
    if (threadIdx.x == 0) {
        int g = *((volatile int*)&d_bar_gen);
        int r = atomicAdd(&d_bar_cnt, 1);
        if (r == nblk - 1) {
            d_bar_cnt = 0;
            __threadfence();
            atomicAdd(&d_bar_gen, 1);
        } else {
            while (*((volatile int*)&d_bar_gen) == g) {}
        }
    }
    __syncthreads();
}

// ---------------------------------------------------------------------------
// prep0: copy h into F slot0, zero counters/gsum, build Wb = W^T bf16 hi/lo
__global__ void k_prep0(const float* __restrict__ h, const float* __restrict__ W0,
                        const float* __restrict__ W1, const float* __restrict__ W2) {
    int i = blockIdx.x * blockDim.x + threadIdx.x;
    if (i < NN * 16) {
        int r = i >> 4, p = i & 15;
        ((float4*)d_F)[(size_t)r * 64 + p] = ((const float4*)h)[i];
    }
    if (i < NN) { d_cnt[i] = 0; d_cur[i] = 0; }
    if (i < NG * D) d_gsum[i] = 0.f;
    if (i < 3 * 16384) {
        int L = i / 16384, r = i - L * 16384;
        int n = r >> 8, k = r & 255;
        const float* W = (L == 0) ? W0 : (L == 1) ? W1 : W2;
        float w = W[k * 64 + n];
        __nv_bfloat16 hi = __float2bfloat16(w);
        __nv_bfloat16 lo = __float2bfloat16(w - __bfloat162float(hi));
        d_Wb[(L * 2 + 0) * 16384 + n * 256 + k] = hi;
        d_Wb[(L * 2 + 1) * 16384 + n * 256 + k] = lo;
    }
}

// prepB (persistent): count -> scan(off,dn) -> CSR fill with fused {src, dn[src]}
__global__ void __launch_bounds__(256, 4) k_prepB(const int* __restrict__ src,
                                                  const int* __restrict__ dst) {
    __shared__ int sh[256];
    int tid = threadIdx.x, b = blockIdx.x;
    int gt = b * 256 + tid;
    const int GS = PB * 256;

    for (int e = gt; e < EE; e += GS) atomicAdd(&d_cnt[dst[e]], 1);
    gbar(PB);

    {
        int i0 = b * CH;
        int v = 0;
        if (tid < CH && i0 + tid < NN) v = d_cnt[i0 + tid];
        sh[tid] = v;
        __syncthreads();
        for (int st = 128; st > 0; st >>= 1) {
            if (tid < st) sh[tid] += sh[tid + st];
            __syncthreads();
        }
        if (tid == 0) d_bsum[b] = sh[0];
    }
    gbar(PB);

    {
        int part = 0;
        for (int i = tid; i < b; i += 256) part += d_bsum[i];
        sh[tid] = part;
        __syncthreads();
        for (int st = 128; st > 0; st >>= 1) {
            if (tid < st) sh[tid] += sh[tid + st];
            __syncthreads();
        }
        int base = sh[0];
        __syncthreads();

        int i0 = b * CH, idx = i0 + tid;
        int v = (tid < CH && idx < NN) ? d_cnt[idx] : 0;
        sh[tid] = v;
        __syncthreads();
        for (int st = 1; st < 256; st <<= 1) {
            int a = (tid >= st) ? sh[tid - st] : 0;
            __syncthreads();
            sh[tid] += a;
            __syncthreads();
        }
        if (tid < CH && idx < NN) {
            d_off[idx] = base + sh[tid] - v;
            d_dn[idx] = rsqrtf(fmaxf((float)v, 1.0f));
        }
        if (gt == 0) d_off[NN] = EE;
    }
    gbar(PB);

    for (int e = gt; e < EE; e += GS) {
        int dd = dst[e];
        int s = src[e];
        int p = atomicAdd(&d_cur[dd], 1);
        d_csrw[d_off[dd] + p] = make_int2(s, __float_as_int(d_dn[s]));
    }
}

// ---------------------------------------------------------------------------
// Hop v3 (measured 29.8us): half-warp per node, fused {src,w}, dual chains.
__global__ void __launch_bounds__(256) k_hop(int hop) {
    int node = blockIdx.x * 16 + (threadIdx.x >> 4);    // grid 6250*16 == NN
    int lane = threadIdx.x & 15;
    int e0 = __ldg(d_off + node);
    int e1 = __ldg(d_off + node + 1);
    const float4* F4 = (const float4*)d_F;
    int slot_in = (hop - 1) * 16 + lane;

    float4 accA = make_float4(0.f, 0.f, 0.f, 0.f);
    float4 accB = make_float4(0.f, 0.f, 0.f, 0.f);

    int2 p0 = make_int2(0, 0), p1 = make_int2(0, 0);
    if (e0 < e1)     p0 = __ldg(d_csrw + e0);
    if (e0 + 1 < e1) p1 = __ldg(d_csrw + e0 + 1);

    int e = e0;
    for (; e + 2 <= e1; e += 2) {
        int2 pn0 = make_int2(0, 0), pn1 = make_int2(0, 0);
        if (e + 2 < e1) pn0 = __ldg(d_csrw + e + 2);
        if (e + 3 < e1) pn1 = __ldg(d_csrw + e + 3);
        float w0 = __int_as_float(p0.y);
        float w1 = __int_as_float(p1.y);
        float4 v0 = __ldg(F4 + (size_t)p0.x * 64 + slot_in);
        float4 v1 = __ldg(F4 + (size_t)p1.x * 64 + slot_in);
        accA.x = fmaf(v0.x, w0, accA.x); accA.y = fmaf(v0.y, w0, accA.y);
        accA.z = fmaf(v0.z, w0, accA.z); accA.w = fmaf(v0.w, w0, accA.w);
        accB.x = fmaf(v1.x, w1, accB.x); accB.y = fmaf(v1.y, w1, accB.y);
        accB.z = fmaf(v1.z, w1, accB.z); accB.w = fmaf(v1.w, w1, accB.w);
        p0 = pn0; p1 = pn1;
    }
    if (e < e1) {
        float w = __int_as_float(p0.y);
        float4 v = __ldg(F4 + (size_t)p0.x * 64 + slot_in);
        accA.x = fmaf(v.x, w, accA.x); accA.y = fmaf(v.y, w, accA.y);
        accA.z = fmaf(v.z, w, accA.z); accA.w = fmaf(v.w, w, accA.w);
    }

    float dn = __ldg(d_dn + node);
    float4 acc;
    acc.x = (accA.x + accB.x) * dn;
    acc.y = (accA.y + accB.y) * dn;
    acc.z = (accA.z + accB.z) * dn;
    acc.w = (accA.w + accB.w) * dn;
    ((float4*)d_F)[(size_t)node * 64 + hop * 16 + lane] = acc;
}

// ---------------------------------------------------------------------------
// GEMM v10: mma.sync bf16 3-product split, software-pipelined staging.
// A prefetched to registers 1 chunk ahead (LDG hidden under MMA); B double-
// buffered via cp.async (wait_group<1>). Inner math identical to v9.
__global__ void __launch_bounds__(128) k_gemmmm(int layer, const float* __restrict__ b) {
    // smem elems (bf16): Ah 2560 | Al 2560 | Bh0 | Bl0 | Bh1 | Bl1  = 30720B
    __shared__ __align__(16) __nv_bfloat16 SM[6 * 64 * 40];
    __nv_bfloat16* Ah = SM;
    __nv_bfloat16* Al = SM + 2560;

    int tid = threadIdx.x;
    int lane = tid & 31, warp = tid >> 5;
    int n0 = blockIdx.x * 64;
    const float4* F4 = (const float4*)d_F;
    const __nv_bfloat16* Wh = d_Wb + (layer * 2 + 0) * 16384;
    const __nv_bfloat16* Wl = d_Wb + (layer * 2 + 1) * 16384;

    unsigned ah_s = smem_u32(Ah), al_s = smem_u32(Al);
    unsigned bh_s[2], bl_s[2];
    bh_s[0] = smem_u32(SM + 5120);
    bl_s[0] = smem_u32(SM + 7680);
    bh_s[1] = smem_u32(SM + 10240);
    bl_s[1] = smem_u32(SM + 12800);

    // per-thread A item coordinates (4 items)
    int nd_[4], f_[4];
    size_t gofs[4];
#pragma unroll
    for (int t = 0; t < 4; t++) {
        int i = tid + t * 128;
        int nd = i >> 3, f = i & 7;
        int node = n0 + nd;
        if (node >= NN) node = NN - 1;
        nd_[t] = nd; f_[t] = f;
        gofs[t] = (size_t)node * 64 + f;
    }

    auto stageB = [&](int ch, int bf) {
#pragma unroll
        for (int t = 0; t < 4; t++) {
            int i = tid + t * 128;
            int part = i >> 8, r = i & 255;
            int n = r >> 2, j = r & 3;
            const __nv_bfloat16* srcp = (part ? Wl : Wh) + n * 256 + ch * 32 + j * 8;
            unsigned dstp = (part ? bl_s[bf] : bh_s[bf]) + (unsigned)(n * 80 + j * 16);
            cpa16(dstp, srcp);
        }
        cpa_commit();
    };

    float c[8][4];
#pragma unroll
    for (int t = 0; t < 8; t++)
#pragma unroll
        for (int j = 0; j < 4; j++) c[t][j] = 0.f;

    int lr = lane & 15;
    int ahalf = (lane >> 4) ? 8 : 0;
    int bg = lane >> 3, blr = lane & 7;
    int bn = ((bg >> 1) ? 8 : 0) + blr;
    int bk = (bg & 1) ? 8 : 0;

    // prologue: A(0) regs + B(0) async
    float4 ra[4];
#pragma unroll
    for (int t = 0; t < 4; t++) ra[t] = __ldg(F4 + gofs[t]);
    stageB(0, 0);

    for (int ch = 0; ch < 8; ch++) {
        int bf = ch & 1;
        float4 rn[4];
        if (ch + 1 < 8) {
#pragma unroll
            for (int t = 0; t < 4; t++)
                rn[t] = __ldg(F4 + gofs[t] + (ch + 1) * 8);   // prefetch A(ch+1)
            stageB(ch + 1, bf ^ 1);
        }
        // convert + STS A(ch)
#pragma unroll
        for (int t = 0; t < 4; t++) {
            float4 v = ra[t];
            __nv_bfloat16 h0 = __float2bfloat16(v.x);
            __nv_bfloat16 h1 = __float2bfloat16(v.y);
            __nv_bfloat16 h2 = __float2bfloat16(v.z);
            __nv_bfloat16 h3 = __float2bfloat16(v.w);
            __nv_bfloat16 hv[4] = {h0, h1, h2, h3};
            __nv_bfloat16 lv[4] = {
                __float2bfloat16(v.x - __bfloat162float(h0)),
                __float2bfloat16(v.y - __bfloat162float(h1)),
                __float2bfloat16(v.z - __bfloat162float(h2)),
                __float2bfloat16(v.w - __bfloat162float(h3))};
            *(uint2*)(Ah + nd_[t] * 40 + f_[t] * 4) = *(uint2*)hv;
            *(uint2*)(Al + nd_[t] * 40 + f_[t] * 4) = *(uint2*)lv;
        }
        if (ch < 7) cpa_wait<1>(); else cpa_wait<0>();
        __syncthreads();

#pragma unroll
        for (int kk = 0; kk < 2; kk++) {
            unsigned a_off = (unsigned)(((warp * 16 + lr) * 40 + kk * 16 + ahalf) * 2);
            unsigned ah0, ah1, ah2, ah3, alo0, alo1, alo2, alo3;
            ldsm4(ah0, ah1, ah2, ah3, ah_s + a_off);
            ldsm4(alo0, alo1, alo2, alo3, al_s + a_off);
#pragma unroll
            for (int nt = 0; nt < 4; nt++) {
                unsigned b_off = (unsigned)(((nt * 16 + bn) * 40 + kk * 16 + bk) * 2);
                unsigned bh0, bh1, bh2, bh3, bl0, bl1, bl2, bl3;
                ldsm4(bh0, bh1, bh2, bh3, bh_s[bf] + b_off);
                ldsm4(bl0, bl1, bl2, bl3, bl_s[bf] + b_off);
                int t0 = 2 * nt, t1 = 2 * nt + 1;
                mma16816(c[t0][0], c[t0][1], c[t0][2], c[t0][3],
                         ah0, ah1, ah2, ah3, bh0, bh1);
                mma16816(c[t1][0], c[t1][1], c[t1][2], c[t1][3],
                         ah0, ah1, ah2, ah3, bh2, bh3);
                mma16816(c[t0][0], c[t0][1], c[t0][2], c[t0][3],
                         alo0, alo1, alo2, alo3, bh0, bh1);
                mma16816(c[t1][0], c[t1][1], c[t1][2], c[t1][3],
                         alo0, alo1, alo2, alo3, bh2, bh3);
                mma16816(c[t0][0], c[t0][1], c[t0][2], c[t0][3],
                         ah0, ah1, ah2, ah3, bl0, bl1);
                mma16816(c[t1][0], c[t1][1], c[t1][2], c[t1][3],
                         ah0, ah1, ah2, ah3, bl2, bl3);
            }
        }
        __syncthreads();   // A buffer reusable next chunk
#pragma unroll
        for (int t = 0; t < 4; t++) ra[t] = rn[t];
    }

    // epilogue: C frags -> smem [64][65] -> bias+relu -> F slot0
    float* Ds = (float*)SM;              // 16640B <= 30720B
    int q = lane & 3, r = lane >> 2;
#pragma unroll
    for (int nt = 0; nt < 8; nt++) {
        int col = nt * 8 + 2 * q;
        int row = warp * 16 + r;
        Ds[row * 65 + col]           = c[nt][0];
        Ds[row * 65 + col + 1]       = c[nt][1];
        Ds[(row + 8) * 65 + col]     = c[nt][2];
        Ds[(row + 8) * 65 + col + 1] = c[nt][3];
    }
    __syncthreads();
    for (int idx = tid; idx < 64 * 64; idx += 128) {
        int row = idx >> 6, cc = idx & 63;
        int node = n0 + row;
        if (node < NN) {
            float v = Ds[row * 65 + cc] + __ldg(b + cc);
            d_F[(size_t)node * CD + cc] = fmaxf(v, 0.f);
        }
    }
}

// ---------------------------------------------------------------------------
// Per-graph sums of F slot0 (graph_ids sorted -> running-accumulator flush)
__global__ void k_gsum(const int* __restrict__ gid) {
    const int CHN = 512;
    int c = threadIdx.x & 63;
    int r0 = threadIdx.x >> 6;
    int nbeg = blockIdx.x * CHN + r0;
    int nend = min(NN, blockIdx.x * CHN + CHN);
    float acc = 0.f;
    int cur = -1;
    for (int n = nbeg; n < nend; n += 4) {
        int g = gid[n];
        if (g != cur) {
            if (cur >= 0) atomicAdd(&d_gsum[cur * D + c], acc);
            cur = g; acc = 0.f;
        }
        acc += d_F[(size_t)n * CD + c];
    }
    if (cur >= 0) atomicAdd(&d_gsum[cur * D + c], acc);
}

// Readout: mean -> @embW + embb -> L2 normalize. One block, 256 threads.
__global__ void k_final(const int* __restrict__ gid,
                        const float* __restrict__ embW,
                        const float* __restrict__ embb,
                        float* __restrict__ out) {
    __shared__ float hg[NG][D];
    __shared__ int bnd[NG + 1];
    __shared__ float nrm[NG];
    int tid = threadIdx.x;

    if (tid <= NG) {
        int lo = 0, hi = NN;
        while (lo < hi) {
            int mid = (lo + hi) >> 1;
            if (gid[mid] < tid) lo = mid + 1; else hi = mid;
        }
        bnd[tid] = lo;
    }
    if (tid < NG) nrm[tid] = 0.f;
    __syncthreads();

    for (int idx = tid; idx < NG * D; idx += 256) {
        int g = idx >> 6;
        float cnt = (float)max(bnd[g + 1] - bnd[g], 1);
        hg[g][idx & 63] = d_gsum[idx] / cnt;
    }
    __syncthreads();

    for (int idx = tid; idx < NG * EMBD; idx += 256) {
        int g = idx >> 7, e = idx & 127;
        float s = embb[e];
#pragma unroll 16
        for (int k = 0; k < D; k++) s += hg[g][k] * embW[k * EMBD + e];
        atomicAdd(&nrm[g], s * s);
    }
    __syncthreads();

    for (int idx = tid; idx < NG * EMBD; idx += 256) {
        int g = idx >> 7, e = idx & 127;
        float s = embb[e];
#pragma unroll 16
        for (int k = 0; k < D; k++) s += hg[g][k] * embW[k * EMBD + e];
        float nv = fmaxf(sqrtf(nrm[g]), 1e-12f);
        out[idx] = s / nv;
    }
}

// ---------------------------------------------------------------------------
extern "C" void kernel_launch(void* const* d_in, const int* in_sizes, int n_in,
                              void* d_out, int out_size) {
    const float* h    = (const float*)d_in[0];
    const int*   src  = (const int*)d_in[1];
    const int*   dst  = (const int*)d_in[2];
    const int*   gid  = (const int*)d_in[3];
    const float* Wl[3] = {(const float*)d_in[4], (const float*)d_in[6], (const float*)d_in[8]};
    const float* bl[3] = {(const float*)d_in[5], (const float*)d_in[7], (const float*)d_in[9]};
    const float* embW = (const float*)d_in[10];
    const float* embb = (const float*)d_in[11];
    float* out = (float*)d_out;
    (void)in_sizes; (void)n_in; (void)out_size;

    k_prep0<<<(NN * 16 + 255) / 256, 256>>>(h, Wl[0], Wl[1], Wl[2]);  // 1
    k_prepB<<<PB, 256>>>(src, dst);                                   // 2

    for (int L = 0; L < 3; L++) {
        k_hop<<<NN / 16, 256>>>(1);
        k_hop<<<NN / 16, 256>>>(2);
        k_hop<<<NN / 16, 256>>>(3);
        k_gemmmm<<<(NN + 63) / 64, 128>>>(L, bl[L]);
    }

    k_gsum<<<(NN + 511) / 512, 256>>>(gid);
    k_final<<<1, 256>>>(gid, embW, embb, out);
}